// round 1
// baseline (speedup 1.0000x reference)
#include <cuda_runtime.h>
#include <cstdint>

#define CN0  400000
#define CN1  40000
#define CN2  4000
#define CIN  128
#define CHID 256
#define COUT 64

// ---- scratch (device globals: no allocation allowed) ----
__device__ float g_agg1[CN1 * CIN];    // 20.5 MB
__device__ float g_deg1[CN1];          // later holds 1/max(deg,1)
__device__ float g_h   [CN1 * CHID];   // 41 MB, relu'd layer-1 output
__device__ float g_agg2[CN2 * CHID];   // 4.1 MB
__device__ float g_deg2[CN2];

// ---------------------------------------------------------------------------
// zero the accumulators
// ---------------------------------------------------------------------------
__global__ void k_zero() {
    int i = blockIdx.x * blockDim.x + threadIdx.x;
    int stride = gridDim.x * blockDim.x;
    float4 z = make_float4(0.f, 0.f, 0.f, 0.f);
    for (int j = i; j < CN1 * CIN / 4; j += stride) ((float4*)g_agg1)[j] = z;
    for (int j = i; j < CN2 * CHID / 4; j += stride) ((float4*)g_agg2)[j] = z;
    for (int j = i; j < CN1; j += stride) g_deg1[j] = 0.f;
    for (int j = i; j < CN2; j += stride) g_deg2[j] = 0.f;
}

__device__ __forceinline__ void red_add_v4(float* p, float4 v) {
    asm volatile("red.global.add.v4.f32 [%0], {%1,%2,%3,%4};"
                 :: "l"(p), "f"(v.x), "f"(v.y), "f"(v.z), "f"(v.w) : "memory");
}

// ---------------------------------------------------------------------------
// layer-1 edge scatter: one warp per edge, 128 floats = 32 lanes x float4
// ---------------------------------------------------------------------------
__global__ void k_scatter1(const float* __restrict__ x,
                           const int* __restrict__ src,
                           const int* __restrict__ dst, int E) {
    int t = blockIdx.x * blockDim.x + threadIdx.x;
    int e = t >> 5;
    if (e >= E) return;
    int lane = t & 31;
    int s = src[e], d = dst[e];
    float4 v = ((const float4*)(x + (size_t)s * CIN))[lane];
    red_add_v4((float*)(((float4*)(g_agg1 + (size_t)d * CIN)) + lane), v);
    if (lane == 0) atomicAdd(g_deg1 + d, 1.0f);
}

// deg -> 1/max(deg,1), in place
__global__ void k_invdeg1() {
    int i = blockIdx.x * blockDim.x + threadIdx.x;
    if (i < CN1) g_deg1[i] = 1.0f / fmaxf(g_deg1[i], 1.0f);
}

// ---------------------------------------------------------------------------
// layer-1 fused GEMM: h = relu([agg1*invdeg | x_root] @ [w_l1;w_r1] + b_l1)
// M=40000, K=256, N=256. BM=BN=128, BK=16, 256 thr, 8x8 per thread.
// ---------------------------------------------------------------------------
__global__ void __launch_bounds__(256) k_gemm1(const float* __restrict__ x,
                                               const float* __restrict__ wl,
                                               const float* __restrict__ wr,
                                               const float* __restrict__ bias) {
    __shared__ float As[16][128];
    __shared__ float Bs[16][128];
    int m0 = blockIdx.y * 128;
    int n0 = blockIdx.x * 128;
    int t  = threadIdx.x;
    int tx = t & 15, ty = t >> 4;
    float acc[8][8] = {};

    for (int k0 = 0; k0 < 256; k0 += 16) {
        // A tile: 128 rows x 16 k's  (512 float4 / 256 thr = 2 each)
        #pragma unroll
        for (int i = 0; i < 2; i++) {
            int idx = t + i * 256;       // 0..511
            int row = idx >> 2;          // 0..127
            int kq  = (idx & 3) * 4;     // 0,4,8,12
            int gm  = m0 + row;
            int gk  = k0 + kq;
            float4 v = make_float4(0.f, 0.f, 0.f, 0.f);
            if (gm < CN1) {
                if (gk < CIN) {
                    float id = g_deg1[gm];
                    float4 a = *(const float4*)(g_agg1 + (size_t)gm * CIN + gk);
                    v = make_float4(a.x * id, a.y * id, a.z * id, a.w * id);
                } else {
                    v = *(const float4*)(x + (size_t)gm * CIN + (gk - CIN));
                }
            }
            As[kq + 0][row] = v.x; As[kq + 1][row] = v.y;
            As[kq + 2][row] = v.z; As[kq + 3][row] = v.w;
        }
        // B tile: 16 k's x 128 n's
        #pragma unroll
        for (int i = 0; i < 2; i++) {
            int idx = t + i * 256;
            int row = idx >> 5;          // 0..15
            int nq  = (idx & 31) * 4;    // 0..124
            int gk  = k0 + row;
            const float* B = (gk < CIN) ? (wl + (size_t)gk * CHID)
                                        : (wr + (size_t)(gk - CIN) * CHID);
            *(float4*)&Bs[row][nq] = *(const float4*)(B + n0 + nq);
        }
        __syncthreads();
        #pragma unroll
        for (int kk = 0; kk < 16; kk++) {
            float a[8], b[8];
            #pragma unroll
            for (int i = 0; i < 8; i++) a[i] = As[kk][ty * 8 + i];
            #pragma unroll
            for (int j = 0; j < 8; j++) b[j] = Bs[kk][tx * 8 + j];
            #pragma unroll
            for (int i = 0; i < 8; i++)
                #pragma unroll
                for (int j = 0; j < 8; j++) acc[i][j] += a[i] * b[j];
        }
        __syncthreads();
    }
    #pragma unroll
    for (int i = 0; i < 8; i++) {
        int gm = m0 + ty * 8 + i;
        if (gm >= CN1) continue;
        #pragma unroll
        for (int j = 0; j < 8; j++) {
            int gn = n0 + tx * 8 + j;
            float v = acc[i][j] + bias[gn];
            g_h[(size_t)gm * CHID + gn] = fmaxf(v, 0.0f);
        }
    }
}

// ---------------------------------------------------------------------------
// layer-2 edge scatter: one warp per edge, 256 floats = 2 x (32 lanes x float4)
// ---------------------------------------------------------------------------
__global__ void k_scatter2(const int* __restrict__ src,
                           const int* __restrict__ dst, int E) {
    int t = blockIdx.x * blockDim.x + threadIdx.x;
    int e = t >> 5;
    if (e >= E) return;
    int lane = t & 31;
    int s = src[e], d = dst[e];
    const float4* hs = (const float4*)(g_h + (size_t)s * CHID);
    float4* ap = (float4*)(g_agg2 + (size_t)d * CHID);
    #pragma unroll
    for (int i = 0; i < 2; i++) {
        float4 v = hs[lane + 32 * i];
        red_add_v4((float*)(ap + lane + 32 * i), v);
    }
    if (lane == 0) atomicAdd(g_deg2 + d, 1.0f);
}

// ---------------------------------------------------------------------------
// layer-2 fused GEMM + log_softmax.
// out = log_softmax([agg2*invdeg | h_root] @ [w_l2;w_r2] + b_l2)
// M=4000, K=512, N=64. Warp per row; lane owns cols {lane, lane+32}.
// ---------------------------------------------------------------------------
__global__ void __launch_bounds__(256) k_gemm2(const float* __restrict__ wl,
                                               const float* __restrict__ wr,
                                               const float* __restrict__ bias,
                                               float* __restrict__ out) {
    __shared__ float As[8][512];
    int warp = threadIdx.x >> 5, lane = threadIdx.x & 31;
    int m = blockIdx.x * 8 + warp;
    if (m >= CN2) return;
    float invd = 1.0f / fmaxf(g_deg2[m], 1.0f);
    #pragma unroll
    for (int i = 0; i < 8; i++)
        As[warp][lane + 32 * i] = g_agg2[(size_t)m * CHID + lane + 32 * i] * invd;
    #pragma unroll
    for (int i = 0; i < 8; i++)
        As[warp][CHID + lane + 32 * i] = g_h[(size_t)m * CHID + lane + 32 * i];
    __syncwarp();

    float acc0 = 0.f, acc1 = 0.f;
    const float* A = As[warp];
    #pragma unroll 8
    for (int k = 0; k < CHID; k++) {
        float a = A[k];
        acc0 += a * wl[k * COUT + lane];
        acc1 += a * wl[k * COUT + lane + 32];
    }
    #pragma unroll 8
    for (int k = 0; k < CHID; k++) {
        float a = A[CHID + k];
        acc0 += a * wr[k * COUT + lane];
        acc1 += a * wr[k * COUT + lane + 32];
    }
    acc0 += bias[lane];
    acc1 += bias[lane + 32];

    // log_softmax over 64 values (2 per lane)
    float mx = fmaxf(acc0, acc1);
    #pragma unroll
    for (int o = 16; o > 0; o >>= 1) mx = fmaxf(mx, __shfl_xor_sync(0xFFFFFFFFu, mx, o));
    float s = expf(acc0 - mx) + expf(acc1 - mx);
    #pragma unroll
    for (int o = 16; o > 0; o >>= 1) s += __shfl_xor_sync(0xFFFFFFFFu, s, o);
    float lse = mx + logf(s);
    out[(size_t)m * COUT + lane]      = acc0 - lse;
    out[(size_t)m * COUT + lane + 32] = acc1 - lse;
}

// ---------------------------------------------------------------------------
extern "C" void kernel_launch(void* const* d_in, const int* in_sizes, int n_in,
                              void* d_out, int out_size) {
    const float* x    = (const float*)d_in[0];
    const int*   src1 = (const int*)d_in[1];
    const int*   dst1 = (const int*)d_in[2];
    const int*   src2 = (const int*)d_in[3];
    const int*   dst2 = (const int*)d_in[4];
    const float* wl1  = (const float*)d_in[5];
    const float* bl1  = (const float*)d_in[6];
    const float* wr1  = (const float*)d_in[7];
    const float* wl2  = (const float*)d_in[8];
    const float* bl2  = (const float*)d_in[9];
    const float* wr2  = (const float*)d_in[10];
    int E1 = in_sizes[1];
    int E2 = in_sizes[3];

    k_zero<<<512, 256>>>();
    k_scatter1<<<(E1 * 32 + 255) / 256, 256>>>(x, src1, dst1, E1);
    k_invdeg1<<<(CN1 + 255) / 256, 256>>>();
    k_gemm1<<<dim3(2, (CN1 + 127) / 128), 256>>>(x, wl1, wr1, bl1);
    k_scatter2<<<(E2 * 32 + 255) / 256, 256>>>(src2, dst2, E2);
    k_gemm2<<<(CN2 + 7) / 8, 256>>>(wl2, wr2, bl2, (float*)d_out);
}

// round 2
// speedup vs baseline: 1.3699x; 1.3699x over previous
#include <cuda_runtime.h>
#include <cstdint>

#define CN0  400000
#define CN1  40000
#define CN2  4000
#define CIN  128
#define CHID 256
#define COUT 64

// ---- scratch (device globals: no allocation allowed) ----
__device__ float g_agg1[CN1 * CIN];    // 20.5 MB
__device__ float g_deg1[CN1];          // later holds 1/max(deg,1)
__device__ float g_h   [CN1 * CHID];   // 41 MB, relu'd layer-1 output
__device__ float g_agg2[CN2 * CHID];   // 4.1 MB
__device__ float g_deg2[CN2];

// ---------------------------------------------------------------------------
// zero the accumulators
// ---------------------------------------------------------------------------
__global__ void k_zero() {
    int i = blockIdx.x * blockDim.x + threadIdx.x;
    int stride = gridDim.x * blockDim.x;
    float4 z = make_float4(0.f, 0.f, 0.f, 0.f);
    for (int j = i; j < CN1 * CIN / 4; j += stride) ((float4*)g_agg1)[j] = z;
    for (int j = i; j < CN2 * CHID / 4; j += stride) ((float4*)g_agg2)[j] = z;
    for (int j = i; j < CN1; j += stride) g_deg1[j] = 0.f;
    for (int j = i; j < CN2; j += stride) g_deg2[j] = 0.f;
}

__device__ __forceinline__ void red_add_v4(float* p, float4 v) {
    asm volatile("red.global.add.v4.f32 [%0], {%1,%2,%3,%4};"
                 :: "l"(p), "f"(v.x), "f"(v.y), "f"(v.z), "f"(v.w) : "memory");
}

// ---------------------------------------------------------------------------
// layer-1 edge scatter: one warp per edge, 128 floats = 32 lanes x float4
// ---------------------------------------------------------------------------
__global__ void k_scatter1(const float* __restrict__ x,
                           const int* __restrict__ src,
                           const int* __restrict__ dst, int E) {
    int t = blockIdx.x * blockDim.x + threadIdx.x;
    int e = t >> 5;
    if (e >= E) return;
    int lane = t & 31;
    int s = src[e], d = dst[e];
    float4 v = ((const float4*)(x + (size_t)s * CIN))[lane];
    red_add_v4((float*)(((float4*)(g_agg1 + (size_t)d * CIN)) + lane), v);
    if (lane == 0) atomicAdd(g_deg1 + d, 1.0f);
}

// deg -> 1/max(deg,1), in place
__global__ void k_invdeg1() {
    int i = blockIdx.x * blockDim.x + threadIdx.x;
    if (i < CN1) g_deg1[i] = 1.0f / fmaxf(g_deg1[i], 1.0f);
}

// ---------------------------------------------------------------------------
// tf32 helpers
// ---------------------------------------------------------------------------
__device__ __forceinline__ uint32_t f2tf(float v) {
    uint32_t r;
    asm("cvt.rna.tf32.f32 %0, %1;" : "=r"(r) : "f"(v));
    return r;
}

__device__ __forceinline__ void mma_tf32(float* c, const uint32_t* a, const uint32_t* b) {
    asm volatile(
        "mma.sync.aligned.m16n8k8.row.col.f32.tf32.tf32.f32 "
        "{%0,%1,%2,%3}, {%4,%5,%6,%7}, {%8,%9}, {%0,%1,%2,%3};"
        : "+f"(c[0]), "+f"(c[1]), "+f"(c[2]), "+f"(c[3])
        : "r"(a[0]), "r"(a[1]), "r"(a[2]), "r"(a[3]), "r"(b[0]), "r"(b[1]));
}

// ---------------------------------------------------------------------------
// layer-1 fused GEMM (tf32 tensor core):
//   h = relu([agg1*invdeg | x_root] @ [w_l1;w_r1] + b_l1)
// M=40000, K=256, N=256. BM=BN=128, BK=32, 256 thr, warp grid 4x2, warp 32x64.
// ---------------------------------------------------------------------------
__global__ void __launch_bounds__(256, 2) k_gemm1(const float* __restrict__ x,
                                                  const float* __restrict__ wl,
                                                  const float* __restrict__ wr,
                                                  const float* __restrict__ bias) {
    __shared__ uint32_t As[32][137];   // [k][m], stride 137: conflict-free stores
    __shared__ uint32_t Bs[32][136];   // [k][n], stride 136: 16B aligned STS.128

    const int t = threadIdx.x;
    const int lane = t & 31, warp = t >> 5;
    const int warp_m = warp & 3;       // 0..3 -> 32-row slab
    const int warp_n = warp >> 2;      // 0..1 -> 64-col slab
    const int m0 = blockIdx.y * 128;
    const int n0 = blockIdx.x * 128;
    const int fr = lane >> 2;          // fragment row group 0..7
    const int fc = lane & 3;           // fragment col group 0..3

    float acc[2][8][4] = {};

    for (int k0 = 0; k0 < CHID; k0 += 32) {
        // ---- A tile: 128 m x 32 k (1024 float4 / 256 thr = 4 each) ----
        #pragma unroll
        for (int i = 0; i < 4; i++) {
            int idx = t + i * 256;      // 0..1023
            int row = idx >> 3;         // m 0..127
            int kq  = (idx & 7) * 4;    // k 0,4,...,28
            int gm  = m0 + row;
            int gk  = k0 + kq;
            float4 v = make_float4(0.f, 0.f, 0.f, 0.f);
            if (gm < CN1) {
                if (gk < CIN) {
                    float id = g_deg1[gm];
                    float4 a = *(const float4*)(g_agg1 + (size_t)gm * CIN + gk);
                    v = make_float4(a.x * id, a.y * id, a.z * id, a.w * id);
                } else {
                    v = *(const float4*)(x + (size_t)gm * CIN + (gk - CIN));
                }
            }
            As[kq + 0][row] = f2tf(v.x);
            As[kq + 1][row] = f2tf(v.y);
            As[kq + 2][row] = f2tf(v.z);
            As[kq + 3][row] = f2tf(v.w);
        }
        // ---- B tile: 32 k x 128 n ----
        #pragma unroll
        for (int i = 0; i < 4; i++) {
            int idx = t + i * 256;
            int krow = idx >> 5;        // 0..31
            int nq   = (idx & 31) * 4;  // 0..124
            int gk   = k0 + krow;
            const float* B = (gk < CIN) ? (wl + (size_t)gk * CHID)
                                        : (wr + (size_t)(gk - CIN) * CHID);
            float4 v = *(const float4*)(B + n0 + nq);
            uint4 u = make_uint4(f2tf(v.x), f2tf(v.y), f2tf(v.z), f2tf(v.w));
            *(uint4*)&Bs[krow][nq] = u;
        }
        __syncthreads();

        #pragma unroll
        for (int ks = 0; ks < 4; ks++) {
            const int kb = ks * 8;
            uint32_t a[2][4], b[8][2];
            #pragma unroll
            for (int mt = 0; mt < 2; mt++) {
                int mr = warp_m * 32 + mt * 16 + fr;
                a[mt][0] = As[kb + fc][mr];
                a[mt][1] = As[kb + fc][mr + 8];
                a[mt][2] = As[kb + fc + 4][mr];
                a[mt][3] = As[kb + fc + 4][mr + 8];
            }
            #pragma unroll
            for (int nt = 0; nt < 8; nt++) {
                int nc = warp_n * 64 + nt * 8 + fr;
                b[nt][0] = Bs[kb + fc][nc];
                b[nt][1] = Bs[kb + fc + 4][nc];
            }
            #pragma unroll
            for (int mt = 0; mt < 2; mt++)
                #pragma unroll
                for (int nt = 0; nt < 8; nt++)
                    mma_tf32(acc[mt][nt], a[mt], b[nt]);
        }
        __syncthreads();
    }

    // ---- epilogue: bias + relu, write g_h ----
    #pragma unroll
    for (int mt = 0; mt < 2; mt++) {
        int gm = m0 + warp_m * 32 + mt * 16 + fr;
        #pragma unroll
        for (int nt = 0; nt < 8; nt++) {
            int gn = n0 + warp_n * 64 + nt * 8 + (fc << 1);
            float b0 = bias[gn], b1 = bias[gn + 1];
            if (gm < CN1) {
                float2 v = make_float2(fmaxf(acc[mt][nt][0] + b0, 0.f),
                                       fmaxf(acc[mt][nt][1] + b1, 0.f));
                *(float2*)(g_h + (size_t)gm * CHID + gn) = v;
            }
            if (gm + 8 < CN1) {
                float2 v = make_float2(fmaxf(acc[mt][nt][2] + b0, 0.f),
                                       fmaxf(acc[mt][nt][3] + b1, 0.f));
                *(float2*)(g_h + (size_t)(gm + 8) * CHID + gn) = v;
            }
        }
    }
}

// ---------------------------------------------------------------------------
// layer-2 edge scatter: one warp per edge, 256 floats = 2 x (32 lanes x float4)
// ---------------------------------------------------------------------------
__global__ void k_scatter2(const int* __restrict__ src,
                           const int* __restrict__ dst, int E) {
    int t = blockIdx.x * blockDim.x + threadIdx.x;
    int e = t >> 5;
    if (e >= E) return;
    int lane = t & 31;
    int s = src[e], d = dst[e];
    const float4* hs = (const float4*)(g_h + (size_t)s * CHID);
    float4* ap = (float4*)(g_agg2 + (size_t)d * CHID);
    #pragma unroll
    for (int i = 0; i < 2; i++) {
        float4 v = hs[lane + 32 * i];
        red_add_v4((float*)(ap + lane + 32 * i), v);
    }
    if (lane == 0) atomicAdd(g_deg2 + d, 1.0f);
}

// ---------------------------------------------------------------------------
// layer-2 fused GEMM + log_softmax.
// out = log_softmax([agg2*invdeg | h_root] @ [w_l2;w_r2] + b_l2)
// M=4000, K=512, N=64. Warp per row; lane owns cols {lane, lane+32}.
// ---------------------------------------------------------------------------
__global__ void __launch_bounds__(256) k_gemm2(const float* __restrict__ wl,
                                               const float* __restrict__ wr,
                                               const float* __restrict__ bias,
                                               float* __restrict__ out) {
    __shared__ float As[8][512];
    int warp = threadIdx.x >> 5, lane = threadIdx.x & 31;
    int m = blockIdx.x * 8 + warp;
    if (m >= CN2) return;
    float invd = 1.0f / fmaxf(g_deg2[m], 1.0f);
    #pragma unroll
    for (int i = 0; i < 8; i++)
        As[warp][lane + 32 * i] = g_agg2[(size_t)m * CHID + lane + 32 * i] * invd;
    #pragma unroll
    for (int i = 0; i < 8; i++)
        As[warp][CHID + lane + 32 * i] = g_h[(size_t)m * CHID + lane + 32 * i];
    __syncwarp();

    float acc0 = 0.f, acc1 = 0.f;
    const float* A = As[warp];
    #pragma unroll 8
    for (int k = 0; k < CHID; k++) {
        float a = A[k];
        acc0 += a * wl[k * COUT + lane];
        acc1 += a * wl[k * COUT + lane + 32];
    }
    #pragma unroll 8
    for (int k = 0; k < CHID; k++) {
        float a = A[CHID + k];
        acc0 += a * wr[k * COUT + lane];
        acc1 += a * wr[k * COUT + lane + 32];
    }
    acc0 += bias[lane];
    acc1 += bias[lane + 32];

    // log_softmax over 64 values (2 per lane)
    float mx = fmaxf(acc0, acc1);
    #pragma unroll
    for (int o = 16; o > 0; o >>= 1) mx = fmaxf(mx, __shfl_xor_sync(0xFFFFFFFFu, mx, o));
    float s = expf(acc0 - mx) + expf(acc1 - mx);
    #pragma unroll
    for (int o = 16; o > 0; o >>= 1) s += __shfl_xor_sync(0xFFFFFFFFu, s, o);
    float lse = mx + logf(s);
    out[(size_t)m * COUT + lane]      = acc0 - lse;
    out[(size_t)m * COUT + lane + 32] = acc1 - lse;
}

// ---------------------------------------------------------------------------
extern "C" void kernel_launch(void* const* d_in, const int* in_sizes, int n_in,
                              void* d_out, int out_size) {
    const float* x    = (const float*)d_in[0];
    const int*   src1 = (const int*)d_in[1];
    const int*   dst1 = (const int*)d_in[2];
    const int*   src2 = (const int*)d_in[3];
    const int*   dst2 = (const int*)d_in[4];
    const float* wl1  = (const float*)d_in[5];
    const float* bl1  = (const float*)d_in[6];
    const float* wr1  = (const float*)d_in[7];
    const float* wl2  = (const float*)d_in[8];
    const float* bl2  = (const float*)d_in[9];
    const float* wr2  = (const float*)d_in[10];
    int E1 = in_sizes[1];
    int E2 = in_sizes[3];

    k_zero<<<512, 256>>>();
    k_scatter1<<<(E1 * 32 + 255) / 256, 256>>>(x, src1, dst1, E1);
    k_invdeg1<<<(CN1 + 255) / 256, 256>>>();
    k_gemm1<<<dim3(2, (CN1 + 127) / 128), 256>>>(x, wl1, wr1, bl1);
    k_scatter2<<<(E2 * 32 + 255) / 256, 256>>>(src2, dst2, E2);
    k_gemm2<<<(CN2 + 7) / 8, 256>>>(wl2, wr2, bl2, (float*)d_out);
}

// round 3
// speedup vs baseline: 1.5332x; 1.1192x over previous
#include <cuda_runtime.h>
#include <cstdint>

#define CN0  400000
#define CN1  40000
#define CN2  4000
#define CIN  128
#define CHID 256
#define COUT 64

// ---- scratch (device globals: no allocation allowed) ----
__device__ float g_agg1[CN1 * CIN];    // 20.5 MB
__device__ float g_deg1[CN1];          // raw degree counts
__device__ float g_h   [CN1 * CHID];   // 41 MB, relu'd layer-1 output
__device__ float g_agg2[CN2 * CHID];   // 4.1 MB
__device__ float g_deg2[CN2];

// ---------------------------------------------------------------------------
// zero the accumulators
// ---------------------------------------------------------------------------
__global__ void k_zero() {
    int i = blockIdx.x * blockDim.x + threadIdx.x;
    int stride = gridDim.x * blockDim.x;
    float4 z = make_float4(0.f, 0.f, 0.f, 0.f);
    for (int j = i; j < CN1 * CIN / 4; j += stride) ((float4*)g_agg1)[j] = z;
    for (int j = i; j < CN2 * CHID / 4; j += stride) ((float4*)g_agg2)[j] = z;
    for (int j = i; j < CN1; j += stride) g_deg1[j] = 0.f;
    for (int j = i; j < CN2; j += stride) g_deg2[j] = 0.f;
}

__device__ __forceinline__ void red_add_v4(float* p, float4 v) {
    asm volatile("red.global.add.v4.f32 [%0], {%1,%2,%3,%4};"
                 :: "l"(p), "f"(v.x), "f"(v.y), "f"(v.z), "f"(v.w) : "memory");
}

// ---------------------------------------------------------------------------
// layer-1 edge scatter: one warp per edge, 128 floats = 32 lanes x float4
// ---------------------------------------------------------------------------
__global__ void k_scatter1(const float* __restrict__ x,
                           const int* __restrict__ src,
                           const int* __restrict__ dst, int E) {
    int t = blockIdx.x * blockDim.x + threadIdx.x;
    int e = t >> 5;
    if (e >= E) return;
    int lane = t & 31;
    int s = src[e], d = dst[e];
    float4 v = ((const float4*)(x + (size_t)s * CIN))[lane];
    red_add_v4((float*)(((float4*)(g_agg1 + (size_t)d * CIN)) + lane), v);
    if (lane == 0) atomicAdd(g_deg1 + d, 1.0f);
}

// ---------------------------------------------------------------------------
// tf32 helpers
// ---------------------------------------------------------------------------
__device__ __forceinline__ uint32_t f2tf(float v) {
    uint32_t r;
    asm("cvt.rna.tf32.f32 %0, %1;" : "=r"(r) : "f"(v));
    return r;
}

__device__ __forceinline__ void mma_tf32(float* c, const uint32_t* a, const uint32_t* b) {
    asm volatile(
        "mma.sync.aligned.m16n8k8.row.col.f32.tf32.tf32.f32 "
        "{%0,%1,%2,%3}, {%4,%5,%6,%7}, {%8,%9}, {%0,%1,%2,%3};"
        : "+f"(c[0]), "+f"(c[1]), "+f"(c[2]), "+f"(c[3])
        : "r"(a[0]), "r"(a[1]), "r"(a[2]), "r"(a[3]), "r"(b[0]), "r"(b[1]));
}

__device__ __forceinline__ uint32_t s2u(const void* p) {
    return (uint32_t)__cvta_generic_to_shared(p);
}

__device__ __forceinline__ void cp16(uint32_t dst, const void* src, int sz) {
    asm volatile("cp.async.cg.shared.global [%0], [%1], 16, %2;"
                 :: "r"(dst), "l"(src), "r"(sz));
}

// ---------------------------------------------------------------------------
// layer-1 fused GEMM (tf32, cp.async double-buffered):
//   h = relu(d*(agg1@wl) + x_root@wr + b_l1),  d = 1/max(deg,1)
// M=40000, K=256 (16 iters of BK=16; iters 0-7: agg1, 8-15: x), N=256.
// BM=BN=128, 256 thr, warp grid 4x2, warp tile 32x64.
// ---------------------------------------------------------------------------
__global__ void __launch_bounds__(256, 2) k_gemm1(const float* __restrict__ x,
                                                  const float* __restrict__ wl,
                                                  const float* __restrict__ wr,
                                                  const float* __restrict__ bias) {
    __shared__ float As[2][128][20];   // [m][k], stride 20: conflict-free frag loads
    __shared__ float Bs[2][16][132];   // [k][n], stride 132

    const int t = threadIdx.x;
    const int lane = t & 31, warp = t >> 5;
    const int warp_m = warp & 3;       // 0..3 -> 32-row slab
    const int warp_n = warp >> 2;      // 0..1 -> 64-col slab
    const int m0 = blockIdx.y * 128;
    const int n0 = blockIdx.x * 128;
    const int fr = lane >> 2;          // 0..7
    const int fc = lane & 3;           // 0..3

    // per-thread load coordinates (2 chunks of 16B for A, 2 for B)
    const int a_row0 = t >> 2,            a_kq0 = (t & 3) * 4;
    const int a_row1 = (t + 256) >> 2,    a_kq1 = a_kq0;
    const int b_k0   = t >> 5,            b_nq0 = (t & 31) * 4;
    const int b_k1   = (t + 256) >> 5,    b_nq1 = b_nq0;

    float acc[2][8][4] = {};

    auto issue = [&](int it, int buf) {
        const int kk = (it & 7) * 16;
        const float* Abase = (it < 8) ? g_agg1 : x;
        const float* Bbase = (it < 8) ? wl : wr;
        {
            int gm = m0 + a_row0;
            int sz = 16, gmc = gm;
            if (gm >= CN1) { gmc = 0; sz = 0; }
            cp16(s2u(&As[buf][a_row0][a_kq0]),
                 Abase + (size_t)gmc * CIN + kk + a_kq0, sz);
        }
        {
            int gm = m0 + a_row1;
            int sz = 16, gmc = gm;
            if (gm >= CN1) { gmc = 0; sz = 0; }
            cp16(s2u(&As[buf][a_row1][a_kq1]),
                 Abase + (size_t)gmc * CIN + kk + a_kq1, sz);
        }
        cp16(s2u(&Bs[buf][b_k0][b_nq0]),
             Bbase + (size_t)(kk + b_k0) * CHID + n0 + b_nq0, 16);
        cp16(s2u(&Bs[buf][b_k1][b_nq1]),
             Bbase + (size_t)(kk + b_k1) * CHID + n0 + b_nq1, 16);
    };

    issue(0, 0);
    asm volatile("cp.async.commit_group;");

    for (int it = 0; it < 16; ++it) {
        const int buf = it & 1;
        if (it + 1 < 16) issue(it + 1, buf ^ 1);
        asm volatile("cp.async.commit_group;");
        asm volatile("cp.async.wait_group 1;");
        __syncthreads();

        const float (*A)[20] = As[buf];
        const float (*B)[132] = Bs[buf];
        #pragma unroll
        for (int ks = 0; ks < 2; ks++) {
            const int kb = ks * 8;
            uint32_t a[2][4], b[8][2];
            #pragma unroll
            for (int mt = 0; mt < 2; mt++) {
                int mr = warp_m * 32 + mt * 16 + fr;
                a[mt][0] = f2tf(A[mr][kb + fc]);
                a[mt][1] = f2tf(A[mr + 8][kb + fc]);
                a[mt][2] = f2tf(A[mr][kb + fc + 4]);
                a[mt][3] = f2tf(A[mr + 8][kb + fc + 4]);
            }
            #pragma unroll
            for (int nt = 0; nt < 8; nt++) {
                int nc = warp_n * 64 + nt * 8 + fr;
                b[nt][0] = f2tf(B[kb + fc][nc]);
                b[nt][1] = f2tf(B[kb + fc + 4][nc]);
            }
            #pragma unroll
            for (int mt = 0; mt < 2; mt++)
                #pragma unroll
                for (int nt = 0; nt < 8; nt++)
                    mma_tf32(acc[mt][nt], a[mt], b[nt]);
        }

        if (it == 7) {
            // finished the agg half: scale accumulators by 1/max(deg,1)
            #pragma unroll
            for (int mt = 0; mt < 2; mt++) {
                int r0 = m0 + warp_m * 32 + mt * 16 + fr;
                int r1 = r0 + 8;
                float d0 = (r0 < CN1) ? 1.0f / fmaxf(g_deg1[r0], 1.0f) : 1.0f;
                float d1 = (r1 < CN1) ? 1.0f / fmaxf(g_deg1[r1], 1.0f) : 1.0f;
                #pragma unroll
                for (int nt = 0; nt < 8; nt++) {
                    acc[mt][nt][0] *= d0; acc[mt][nt][1] *= d0;
                    acc[mt][nt][2] *= d1; acc[mt][nt][3] *= d1;
                }
            }
        }
        __syncthreads();
    }

    // ---- epilogue: bias + relu, write g_h ----
    #pragma unroll
    for (int mt = 0; mt < 2; mt++) {
        int gm = m0 + warp_m * 32 + mt * 16 + fr;
        #pragma unroll
        for (int nt = 0; nt < 8; nt++) {
            int gn = n0 + warp_n * 64 + nt * 8 + (fc << 1);
            float b0 = bias[gn], b1 = bias[gn + 1];
            if (gm < CN1) {
                float2 v = make_float2(fmaxf(acc[mt][nt][0] + b0, 0.f),
                                       fmaxf(acc[mt][nt][1] + b1, 0.f));
                *(float2*)(g_h + (size_t)gm * CHID + gn) = v;
            }
            if (gm + 8 < CN1) {
                float2 v = make_float2(fmaxf(acc[mt][nt][2] + b0, 0.f),
                                       fmaxf(acc[mt][nt][3] + b1, 0.f));
                *(float2*)(g_h + (size_t)(gm + 8) * CHID + gn) = v;
            }
        }
    }
}

// ---------------------------------------------------------------------------
// layer-2 edge scatter: one warp per edge, 256 floats = 2 x (32 lanes x float4)
// ---------------------------------------------------------------------------
__global__ void k_scatter2(const int* __restrict__ src,
                           const int* __restrict__ dst, int E) {
    int t = blockIdx.x * blockDim.x + threadIdx.x;
    int e = t >> 5;
    if (e >= E) return;
    int lane = t & 31;
    int s = src[e], d = dst[e];
    const float4* hs = (const float4*)(g_h + (size_t)s * CHID);
    float4* ap = (float4*)(g_agg2 + (size_t)d * CHID);
    #pragma unroll
    for (int i = 0; i < 2; i++) {
        float4 v = hs[lane + 32 * i];
        red_add_v4((float*)(ap + lane + 32 * i), v);
    }
    if (lane == 0) atomicAdd(g_deg2 + d, 1.0f);
}

// ---------------------------------------------------------------------------
// layer-2 fused GEMM + log_softmax.
// out = log_softmax([agg2*invdeg | h_root] @ [w_l2;w_r2] + b_l2)
// M=4000, K=512, N=64. Warp per row; lane owns cols {lane, lane+32}.
// ---------------------------------------------------------------------------
__global__ void __launch_bounds__(256) k_gemm2(const float* __restrict__ wl,
                                               const float* __restrict__ wr,
                                               const float* __restrict__ bias,
                                               float* __restrict__ out) {
    __shared__ float As[8][512];
    int warp = threadIdx.x >> 5, lane = threadIdx.x & 31;
    int m = blockIdx.x * 8 + warp;
    if (m >= CN2) return;
    float invd = 1.0f / fmaxf(g_deg2[m], 1.0f);
    #pragma unroll
    for (int i = 0; i < 8; i++)
        As[warp][lane + 32 * i] = g_agg2[(size_t)m * CHID + lane + 32 * i] * invd;
    #pragma unroll
    for (int i = 0; i < 8; i++)
        As[warp][CHID + lane + 32 * i] = g_h[(size_t)m * CHID + lane + 32 * i];
    __syncwarp();

    float acc0 = 0.f, acc1 = 0.f;
    const float* A = As[warp];
    #pragma unroll 8
    for (int k = 0; k < CHID; k++) {
        float a = A[k];
        acc0 += a * wl[k * COUT + lane];
        acc1 += a * wl[k * COUT + lane + 32];
    }
    #pragma unroll 8
    for (int k = 0; k < CHID; k++) {
        float a = A[CHID + k];
        acc0 += a * wr[k * COUT + lane];
        acc1 += a * wr[k * COUT + lane + 32];
    }
    acc0 += bias[lane];
    acc1 += bias[lane + 32];

    // log_softmax over 64 values (2 per lane)
    float mx = fmaxf(acc0, acc1);
    #pragma unroll
    for (int o = 16; o > 0; o >>= 1) mx = fmaxf(mx, __shfl_xor_sync(0xFFFFFFFFu, mx, o));
    float s = expf(acc0 - mx) + expf(acc1 - mx);
    #pragma unroll
    for (int o = 16; o > 0; o >>= 1) s += __shfl_xor_sync(0xFFFFFFFFu, s, o);
    float lse = mx + logf(s);
    out[(size_t)m * COUT + lane]      = acc0 - lse;
    out[(size_t)m * COUT + lane + 32] = acc1 - lse;
}

// ---------------------------------------------------------------------------
extern "C" void kernel_launch(void* const* d_in, const int* in_sizes, int n_in,
                              void* d_out, int out_size) {
    const float* x    = (const float*)d_in[0];
    const int*   src1 = (const int*)d_in[1];
    const int*   dst1 = (const int*)d_in[2];
    const int*   src2 = (const int*)d_in[3];
    const int*   dst2 = (const int*)d_in[4];
    const float* wl1  = (const float*)d_in[5];
    const float* bl1  = (const float*)d_in[6];
    const float* wr1  = (const float*)d_in[7];
    const float* wl2  = (const float*)d_in[8];
    const float* bl2  = (const float*)d_in[9];
    const float* wr2  = (const float*)d_in[10];
    int E1 = in_sizes[1];
    int E2 = in_sizes[3];

    k_zero<<<512, 256>>>();
    k_scatter1<<<(E1 * 32 + 255) / 256, 256>>>(x, src1, dst1, E1);
    k_gemm1<<<dim3(2, (CN1 + 127) / 128), 256>>>(x, wl1, wr1, bl1);
    k_scatter2<<<(E2 * 32 + 255) / 256, 256>>>(src2, dst2, E2);
    k_gemm2<<<(CN2 + 7) / 8, 256>>>(wl2, wr2, bl2, (float*)d_out);
}